// round 2
// baseline (speedup 1.0000x reference)
#include <cuda_runtime.h>
#include <cstdint>

// ---------------- problem constants ----------------
#define N_NODES 100000
#define N_EDGES 1600000
#define C_IN    500
#define C       40        // n_classes
#define H       64        // hidden
#define ALPHA   0.1f
#define K_HOPS  10

// ---------------- static scratch (no allocations allowed) ----------------
__device__ float g_h0[N_NODES * C];
__device__ float g_bufA[N_NODES * C];
__device__ float g_bufB[N_NODES * C];
__device__ int   g_deg[2 * N_NODES];        // [0..N) = deg_out, [N..2N) = deg_in
__device__ float g_inv_out[N_NODES];
__device__ float g_inv_in[N_NODES];
__device__ int   g_off[N_NODES + 1];
__device__ int   g_cursor[N_NODES];
__device__ int2  g_csr[N_EDGES];            // (src, bits(norm))

// ============================================================
// 1) fused: scores = x@Wb+bb ; probs = softmax(scores)
//    h0 = relu(probs@W1+b1)@W2+b2
//    256 rows/block, 1 row/thread. Wb + x-tiles in SMEM.
// ============================================================
#define GB_ROWS 256
#define GB_KT   64
#define GEMM_SMEM ((C_IN * C + GB_ROWS * (GB_KT + 1)) * 4)

__global__ __launch_bounds__(GB_ROWS) void gemm_mlp_kernel(
    const float* __restrict__ x, const float* __restrict__ Wb,
    const float* __restrict__ bb, float* __restrict__ scores,
    const float* __restrict__ W1, const float* __restrict__ b1,
    const float* __restrict__ W2, const float* __restrict__ b2)
{
    extern __shared__ float sh[];
    float* Ws = sh;                      // [500][40]
    float* xs = sh + C_IN * C;           // [256][65]
    __shared__ float bs[C];
    __shared__ float W1s[C * H];         // [40][64]
    __shared__ float W2s[H * C];         // [64][40]
    __shared__ float b1s[H];
    __shared__ float b2s[C];

    const int tid = threadIdx.x;
    for (int i = tid; i < C_IN * C; i += GB_ROWS) Ws[i] = Wb[i];
    for (int i = tid; i < C * H; i += GB_ROWS) W1s[i] = W1[i];
    for (int i = tid; i < H * C; i += GB_ROWS) W2s[i] = W2[i];
    if (tid < C) bs[tid] = bb[tid];
    if (tid < H) b1s[tid] = b1[tid];
    if (tid < C) b2s[tid] = b2[tid];

    const int row = blockIdx.x * GB_ROWS + tid;
    float acc[C];
#pragma unroll
    for (int c = 0; c < C; c++) acc[c] = 0.f;

    const int warp = tid >> 5, lane = tid & 31;

    for (int k0 = 0; k0 < C_IN; k0 += GB_KT) {
        const int kt = min(GB_KT, C_IN - k0);
        __syncthreads();
        for (int r = warp; r < GB_ROWS; r += 8) {
            const int grow = blockIdx.x * GB_ROWS + r;
            if (grow < N_NODES) {
                const float* xr = x + (size_t)grow * C_IN + k0;
                for (int k = lane; k < kt; k += 32)
                    xs[r * (GB_KT + 1) + k] = xr[k];
            } else {
                for (int k = lane; k < kt; k += 32)
                    xs[r * (GB_KT + 1) + k] = 0.f;
            }
        }
        __syncthreads();

        const float4* Ws4 = (const float4*)Ws;   // [500][10]
#pragma unroll 4
        for (int k = 0; k < kt; k++) {
            const float xv = xs[tid * (GB_KT + 1) + k];
            const float4* wrow = Ws4 + (size_t)(k0 + k) * (C / 4);
#pragma unroll
            for (int c4 = 0; c4 < C / 4; c4++) {
                const float4 w = wrow[c4];
                acc[c4 * 4 + 0] += xv * w.x;
                acc[c4 * 4 + 1] += xv * w.y;
                acc[c4 * 4 + 2] += xv * w.z;
                acc[c4 * 4 + 3] += xv * w.w;
            }
        }
    }

    if (row >= N_NODES) return;

    // ---- epilogue: scores, softmax, MLP ----
    float m = -1e30f;
#pragma unroll
    for (int c = 0; c < C; c++) { acc[c] += bs[c]; m = fmaxf(m, acc[c]); }

    float4* out4 = (float4*)(scores + (size_t)row * C);
#pragma unroll
    for (int c4 = 0; c4 < C / 4; c4++)
        out4[c4] = make_float4(acc[c4*4+0], acc[c4*4+1], acc[c4*4+2], acc[c4*4+3]);

    float s = 0.f;
#pragma unroll
    for (int c = 0; c < C; c++) { acc[c] = __expf(acc[c] - m); s += acc[c]; }
    const float inv = 1.f / s;
#pragma unroll
    for (int c = 0; c < C; c++) acc[c] *= inv;   // acc = probs

    float o[C];
#pragma unroll
    for (int c = 0; c < C; c++) o[c] = b2s[c];

#pragma unroll
    for (int half = 0; half < 2; half++) {
        float h1[32];
#pragma unroll
        for (int j = 0; j < 32; j++) h1[j] = b1s[half * 32 + j];
        for (int i = 0; i < C; i++) {
            const float pv = acc[i];
#pragma unroll
            for (int j = 0; j < 32; j++)
                h1[j] += pv * W1s[i * H + half * 32 + j];
        }
#pragma unroll
        for (int j = 0; j < 32; j++) {
            const float hv = fmaxf(h1[j], 0.f);
#pragma unroll
            for (int c = 0; c < C; c++)
                o[c] += hv * W2s[(half * 32 + j) * C + c];
        }
    }

    float4* hrow4 = (float4*)(g_h0 + (size_t)row * C);
#pragma unroll
    for (int c4 = 0; c4 < C / 4; c4++)
        hrow4[c4] = make_float4(o[c4*4+0], o[c4*4+1], o[c4*4+2], o[c4*4+3]);
}

// ============================================================
// 2) degrees
// ============================================================
__global__ void deg_kernel(const int* __restrict__ src, const int* __restrict__ dst)
{
    const int e = blockIdx.x * blockDim.x + threadIdx.x;
    if (e < N_EDGES) {
        atomicAdd(&g_deg[src[e]], 1);
        atomicAdd(&g_deg[N_NODES + dst[e]], 1);
    }
}

// ============================================================
// 3) fused: inv-sqrt degrees + exclusive scan of deg_in -> offsets + cursor
//    single block, 1024 threads
// ============================================================
#define SCAN_T 1024
__global__ __launch_bounds__(SCAN_T) void scan_fused_kernel()
{
    __shared__ int part[SCAN_T];
    const int t = threadIdx.x;

    for (int i = t; i < N_NODES; i += SCAN_T) {
        const int d_o = g_deg[i];
        const int d_i = g_deg[N_NODES + i];
        g_inv_out[i] = d_o > 0 ? rsqrtf((float)d_o) : 0.f;
        g_inv_in[i]  = d_i > 0 ? rsqrtf((float)d_i) : 0.f;
    }

    const int CH = (N_NODES + SCAN_T - 1) / SCAN_T;
    const int base = t * CH;
    int s = 0;
    for (int i = 0; i < CH; i++) {
        const int idx = base + i;
        if (idx < N_NODES) s += g_deg[N_NODES + idx];
    }
    part[t] = s;
    __syncthreads();
    for (int o = 1; o < SCAN_T; o <<= 1) {
        const int v = (t >= o) ? part[t - o] : 0;
        __syncthreads();
        part[t] += v;
        __syncthreads();
    }
    int excl = part[t] - s;
    for (int i = 0; i < CH; i++) {
        const int idx = base + i;
        if (idx < N_NODES) {
            g_off[idx] = excl;
            g_cursor[idx] = excl;
            excl += g_deg[N_NODES + idx];
        }
    }
    if (t == SCAN_T - 1) g_off[N_NODES] = part[SCAN_T - 1];
}

// ============================================================
// 4) CSR fill (single 8B scatter per edge)
// ============================================================
__global__ void fill_csr_kernel(const int* __restrict__ src, const int* __restrict__ dst)
{
    const int e = blockIdx.x * blockDim.x + threadIdx.x;
    if (e < N_EDGES) {
        const int s = src[e];
        const int d = dst[e];
        const int pos = atomicAdd(&g_cursor[d], 1);
        g_csr[pos] = make_int2(s, __float_as_int(g_inv_out[s] * g_inv_in[d]));
    }
}

// ============================================================
// 5) one APPNP hop: float4 channel packing, 3 nodes per warp,
//    10 lanes per node (one float4 each), pure gather.
// ============================================================
#define HOP_BS 256
#define NODES_PER_WARP 3
#define NODES_PER_BLOCK ((HOP_BS / 32) * NODES_PER_WARP)

__global__ __launch_bounds__(HOP_BS) void hop_kernel(
    const float* __restrict__ hin, const float* __restrict__ h0,
    float* __restrict__ hout)
{
    const int warp = threadIdx.x >> 5;
    const int lane = threadIdx.x & 31;
    const int sub = lane / 10;           // 0..2 active, sub==3 (lanes 30,31) idle
    const int q = lane - sub * 10;       // float4 index within row
    if (sub >= NODES_PER_WARP) return;

    const int node = (blockIdx.x * (HOP_BS / 32) + warp) * NODES_PER_WARP + sub;
    if (node >= N_NODES) return;

    const int beg = g_off[node];
    const int end = g_off[node + 1];

    float4 acc = make_float4(0.f, 0.f, 0.f, 0.f);
#pragma unroll 4
    for (int e = beg; e < end; e++) {
        const int2 en = g_csr[e];                    // broadcast within sub
        const float nrm = __int_as_float(en.y);
        const float4 hv = ((const float4*)(hin + (size_t)en.x * C))[q];
        acc.x += nrm * hv.x;
        acc.y += nrm * hv.y;
        acc.z += nrm * hv.z;
        acc.w += nrm * hv.w;
    }

    const float4 h0v = ((const float4*)(h0 + (size_t)node * C))[q];
    float4 o;
    o.x = (1.f - ALPHA) * acc.x + ALPHA * h0v.x;
    o.y = (1.f - ALPHA) * acc.y + ALPHA * h0v.y;
    o.z = (1.f - ALPHA) * acc.z + ALPHA * h0v.z;
    o.w = (1.f - ALPHA) * acc.w + ALPHA * h0v.w;
    ((float4*)(hout + (size_t)node * C))[q] = o;
}

// ============================================================
// launch
// ============================================================
extern "C" void kernel_launch(void* const* d_in, const int* in_sizes, int n_in,
                              void* d_out, int out_size)
{
    const float* x  = (const float*)d_in[0];
    const int*   ei = (const int*)d_in[1];
    const float* Wb = (const float*)d_in[2];
    const float* bb = (const float*)d_in[3];
    const float* W1 = (const float*)d_in[4];
    const float* b1 = (const float*)d_in[5];
    const float* W2 = (const float*)d_in[6];
    const float* b2 = (const float*)d_in[7];

    float* out = (float*)d_out;
    float* adjust = out;                              // [N, 40]
    float* scores = out + (size_t)N_NODES * C;        // [N, 40]

    const int* src = ei;
    const int* dst = ei + N_EDGES;

    cudaFuncSetAttribute(gemm_mlp_kernel,
                         cudaFuncAttributeMaxDynamicSharedMemorySize, GEMM_SMEM);

    float *h0p, *Ap, *Bp;
    int *degp;
    cudaGetSymbolAddress((void**)&h0p, g_h0);
    cudaGetSymbolAddress((void**)&Ap, g_bufA);
    cudaGetSymbolAddress((void**)&Bp, g_bufB);
    cudaGetSymbolAddress((void**)&degp, g_deg);

    // launch order chosen so ncu (-s 5 -c 1) captures the first hop_kernel:
    // memset(1), deg(2), scan_fused(3), fill(4), gemm_mlp(5), hop0(6)
    cudaMemsetAsync(degp, 0, 2 * N_NODES * sizeof(int), 0);

    deg_kernel<<<(N_EDGES + 255) / 256, 256>>>(src, dst);
    scan_fused_kernel<<<1, SCAN_T>>>();
    fill_csr_kernel<<<(N_EDGES + 255) / 256, 256>>>(src, dst);

    gemm_mlp_kernel<<<(N_NODES + GB_ROWS - 1) / GB_ROWS, GB_ROWS, GEMM_SMEM>>>(
        x, Wb, bb, scores, W1, b1, W2, b2);

    const int hop_grid = (N_NODES + NODES_PER_BLOCK - 1) / NODES_PER_BLOCK;
    const float* hin = h0p;
    for (int k = 0; k < K_HOPS; k++) {
        float* o = (k == K_HOPS - 1) ? adjust : ((k % 2 == 0) ? Ap : Bp);
        hop_kernel<<<hop_grid, HOP_BS>>>(hin, h0p, o);
        hin = o;
    }
}

// round 3
// speedup vs baseline: 1.3453x; 1.3453x over previous
#include <cuda_runtime.h>
#include <cstdint>

// ---------------- problem constants ----------------
#define N_NODES 100000
#define N_EDGES 1600000
#define C_IN    500
#define C       40        // n_classes
#define H       64        // hidden
#define ALPHA   0.1f
#define K_HOPS  10

// ---------------- static scratch (no allocations allowed) ----------------
__device__ float g_h0[N_NODES * C];
__device__ float g_bufA[N_NODES * C];
__device__ float g_bufB[N_NODES * C];
__device__ int   g_deg[2 * N_NODES];        // [0..N) = deg_out, [N..2N) = deg_in
__device__ float g_inv_out[N_NODES];
__device__ float g_inv_in[N_NODES];
__device__ int   g_off[N_NODES + 1];
__device__ int   g_cursor[N_NODES];
__device__ int2  g_csr[N_EDGES];            // (src, bits(norm))

// ============================================================
// 1) scores = x @ Wb + bb   [N, 40]
//    128 rows/block (1 row/thread), K-tiles of 64.
//    W tile + x tile in SMEM (43.5KB) -> 5 CTAs/SM.
//    Accumulators packed as f32x2; fma.rn.f32x2 (FFMA2).
// ============================================================
#define GB_ROWS   128
#define GB_KT     64
#define XS_STRIDE 65                       // odd -> conflict-free lane access
#define GEMM_SMEM ((GB_KT * C + GB_ROWS * XS_STRIDE) * 4)

__global__ __launch_bounds__(GB_ROWS, 5) void gemm_kernel(
    const float* __restrict__ x, const float* __restrict__ Wb,
    const float* __restrict__ bb, float* __restrict__ scores)
{
    extern __shared__ float sh[];
    float* Wt = sh;                        // [64][40] current K-tile of W
    float* xs = sh + GB_KT * C;            // [128][65]
    __shared__ float bs[C];

    const int tid = threadIdx.x;
    if (tid < C) bs[tid] = bb[tid];

    const int row = blockIdx.x * GB_ROWS + tid;
    const int warp = tid >> 5, lane = tid & 31;

    unsigned long long acc2[C / 2];        // 20 packed f32x2 accumulators
#pragma unroll
    for (int j = 0; j < C / 2; j++) acc2[j] = 0ull;

    for (int k0 = 0; k0 < C_IN; k0 += GB_KT) {
        const int kt = min(GB_KT, C_IN - k0);   // 64,...,64,52 (both %4==0)
        __syncthreads();
        // stage W tile (contiguous rows k0..k0+kt-1, all 40 cols)
        for (int i = tid; i < kt * C; i += GB_ROWS)
            Wt[i] = Wb[k0 * C + i];
        // stage x tile
        for (int r = warp; r < GB_ROWS; r += GB_ROWS / 32) {
            const int grow = blockIdx.x * GB_ROWS + r;
            if (grow < N_NODES) {
                const float* xr = x + (size_t)grow * C_IN + k0;
                for (int k = lane; k < kt; k += 32)
                    xs[r * XS_STRIDE + k] = xr[k];
            } else {
                for (int k = lane; k < kt; k += 32)
                    xs[r * XS_STRIDE + k] = 0.f;
            }
        }
        __syncthreads();

#pragma unroll 4
        for (int k = 0; k < kt; k++) {
            const float xv = xs[tid * XS_STRIDE + k];
            unsigned long long x2;
            asm("mov.b64 %0, {%1, %1};" : "=l"(x2) : "f"(xv));
            const ulonglong2* wr = (const ulonglong2*)(Wt + k * C);
#pragma unroll
            for (int j = 0; j < C / 4; j++) {
                const ulonglong2 w = wr[j];   // LDS.128 broadcast: 2 packed pairs
                asm("fma.rn.f32x2 %0, %1, %2, %0;"
                    : "+l"(acc2[j * 2 + 0]) : "l"(w.x), "l"(x2));
                asm("fma.rn.f32x2 %0, %1, %2, %0;"
                    : "+l"(acc2[j * 2 + 1]) : "l"(w.y), "l"(x2));
            }
        }
    }

    if (row >= N_NODES) return;

    float out[C];
#pragma unroll
    for (int j = 0; j < C / 2; j++) {
        float lo, hi;
        asm("mov.b64 {%0, %1}, %2;" : "=f"(lo), "=f"(hi) : "l"(acc2[j]));
        out[2 * j + 0] = lo + bs[2 * j + 0];
        out[2 * j + 1] = hi + bs[2 * j + 1];
    }
    float4* out4 = (float4*)(scores + (size_t)row * C);
#pragma unroll
    for (int c4 = 0; c4 < C / 4; c4++)
        out4[c4] = make_float4(out[c4*4+0], out[c4*4+1], out[c4*4+2], out[c4*4+3]);
}

// ============================================================
// 2) h0 = relu(softmax(scores) @ W1 + b1) @ W2 + b2
//    1 node/thread; probs staged in SMEM lane-striped.
// ============================================================
#define MLP_BS 128
__global__ __launch_bounds__(MLP_BS) void mlp_kernel(
    const float* __restrict__ scores, float* __restrict__ h0,
    const float* __restrict__ W1, const float* __restrict__ b1,
    const float* __restrict__ W2, const float* __restrict__ b2)
{
    __shared__ float W1s[C * H];      // [40][64]
    __shared__ float W2s[H * C];      // [64][40]
    __shared__ float b1s[H];
    __shared__ float b2s[C];
    __shared__ float p_sh[C * MLP_BS];

    const int tid = threadIdx.x;
    for (int i = tid; i < C * H; i += MLP_BS) W1s[i] = W1[i];
    for (int i = tid; i < H * C; i += MLP_BS) W2s[i] = W2[i];
    if (tid < H) b1s[tid] = b1[tid];
    if (tid < C) b2s[tid] = b2[tid];
    __syncthreads();

    const int node = blockIdx.x * MLP_BS + tid;
    if (node >= N_NODES) return;

    const float4* sc4 = (const float4*)(scores + (size_t)node * C);
    float m = -1e30f;
#pragma unroll
    for (int q = 0; q < C / 4; q++) {
        const float4 v = sc4[q];
        p_sh[(q * 4 + 0) * MLP_BS + tid] = v.x;
        p_sh[(q * 4 + 1) * MLP_BS + tid] = v.y;
        p_sh[(q * 4 + 2) * MLP_BS + tid] = v.z;
        p_sh[(q * 4 + 3) * MLP_BS + tid] = v.w;
        m = fmaxf(m, fmaxf(fmaxf(v.x, v.y), fmaxf(v.z, v.w)));
    }
    float s = 0.f;
    for (int i = 0; i < C; i++) {
        const float e = __expf(p_sh[i * MLP_BS + tid] - m);
        p_sh[i * MLP_BS + tid] = e;
        s += e;
    }
    const float inv = 1.f / s;

    float h1[H];
#pragma unroll
    for (int j = 0; j < H; j++) h1[j] = b1s[j];
    for (int i = 0; i < C; i++) {
        const float pv = p_sh[i * MLP_BS + tid] * inv;
#pragma unroll
        for (int j = 0; j < H; j++) h1[j] += pv * W1s[i * H + j];
    }
#pragma unroll
    for (int j = 0; j < H; j++) h1[j] = fmaxf(h1[j], 0.f);

    float* hrow = h0 + (size_t)node * C;
    for (int c = 0; c < C; c++) {
        float a = b2s[c];
#pragma unroll
        for (int j = 0; j < H; j++) a += h1[j] * W2s[j * C + c];
        hrow[c] = a;
    }
}

// ============================================================
// 3) degrees
// ============================================================
__global__ void deg_kernel(const int* __restrict__ src, const int* __restrict__ dst)
{
    const int e = blockIdx.x * blockDim.x + threadIdx.x;
    if (e < N_EDGES) {
        atomicAdd(&g_deg[src[e]], 1);
        atomicAdd(&g_deg[N_NODES + dst[e]], 1);
    }
}

// ============================================================
// 4) fused: inv-sqrt + exclusive scan -> offsets + cursor
// ============================================================
#define SCAN_T 1024
__global__ __launch_bounds__(SCAN_T) void scan_fused_kernel()
{
    __shared__ int part[SCAN_T];
    const int t = threadIdx.x;

    for (int i = t; i < N_NODES; i += SCAN_T) {
        const int d_o = g_deg[i];
        const int d_i = g_deg[N_NODES + i];
        g_inv_out[i] = d_o > 0 ? rsqrtf((float)d_o) : 0.f;
        g_inv_in[i]  = d_i > 0 ? rsqrtf((float)d_i) : 0.f;
    }

    const int CH = (N_NODES + SCAN_T - 1) / SCAN_T;
    const int base = t * CH;
    int s = 0;
    for (int i = 0; i < CH; i++) {
        const int idx = base + i;
        if (idx < N_NODES) s += g_deg[N_NODES + idx];
    }
    part[t] = s;
    __syncthreads();
    for (int o = 1; o < SCAN_T; o <<= 1) {
        const int v = (t >= o) ? part[t - o] : 0;
        __syncthreads();
        part[t] += v;
        __syncthreads();
    }
    int excl = part[t] - s;
    for (int i = 0; i < CH; i++) {
        const int idx = base + i;
        if (idx < N_NODES) {
            g_off[idx] = excl;
            g_cursor[idx] = excl;
            excl += g_deg[N_NODES + idx];
        }
    }
    if (t == SCAN_T - 1) g_off[N_NODES] = part[SCAN_T - 1];
}

// ============================================================
// 5) CSR fill (single 8B scatter per edge)
// ============================================================
__global__ void fill_csr_kernel(const int* __restrict__ src, const int* __restrict__ dst)
{
    const int e = blockIdx.x * blockDim.x + threadIdx.x;
    if (e < N_EDGES) {
        const int s = src[e];
        const int d = dst[e];
        const int pos = atomicAdd(&g_cursor[d], 1);
        g_csr[pos] = make_int2(s, __float_as_int(g_inv_out[s] * g_inv_in[d]));
    }
}

// ============================================================
// 6) one APPNP hop: float4 channel packing, 3 nodes/warp,
//    10 lanes/node, pure gather (no atomics).
// ============================================================
#define HOP_BS 256
#define NODES_PER_WARP 3
#define NODES_PER_BLOCK ((HOP_BS / 32) * NODES_PER_WARP)

__global__ __launch_bounds__(HOP_BS) void hop_kernel(
    const float* __restrict__ hin, const float* __restrict__ h0,
    float* __restrict__ hout)
{
    const int warp = threadIdx.x >> 5;
    const int lane = threadIdx.x & 31;
    const int sub = lane / 10;           // 0..2 active, lanes 30,31 idle
    const int q = lane - sub * 10;
    if (sub >= NODES_PER_WARP) return;

    const int node = (blockIdx.x * (HOP_BS / 32) + warp) * NODES_PER_WARP + sub;
    if (node >= N_NODES) return;

    const int beg = g_off[node];
    const int end = g_off[node + 1];

    float4 acc = make_float4(0.f, 0.f, 0.f, 0.f);
#pragma unroll 4
    for (int e = beg; e < end; e++) {
        const int2 en = __ldg(&g_csr[e]);
        const float nrm = __int_as_float(en.y);
        const float4 hv = __ldg((const float4*)(hin + (size_t)en.x * C) + q);
        acc.x += nrm * hv.x;
        acc.y += nrm * hv.y;
        acc.z += nrm * hv.z;
        acc.w += nrm * hv.w;
    }

    const float4 h0v = __ldg((const float4*)(h0 + (size_t)node * C) + q);
    float4 o;
    o.x = (1.f - ALPHA) * acc.x + ALPHA * h0v.x;
    o.y = (1.f - ALPHA) * acc.y + ALPHA * h0v.y;
    o.z = (1.f - ALPHA) * acc.z + ALPHA * h0v.z;
    o.w = (1.f - ALPHA) * acc.w + ALPHA * h0v.w;
    ((float4*)(hout + (size_t)node * C))[q] = o;
}

// ============================================================
// launch
// ============================================================
extern "C" void kernel_launch(void* const* d_in, const int* in_sizes, int n_in,
                              void* d_out, int out_size)
{
    const float* x  = (const float*)d_in[0];
    const int*   ei = (const int*)d_in[1];
    const float* Wb = (const float*)d_in[2];
    const float* bb = (const float*)d_in[3];
    const float* W1 = (const float*)d_in[4];
    const float* b1 = (const float*)d_in[5];
    const float* W2 = (const float*)d_in[6];
    const float* b2 = (const float*)d_in[7];

    float* out = (float*)d_out;
    float* adjust = out;                              // [N, 40]
    float* scores = out + (size_t)N_NODES * C;        // [N, 40]

    const int* src = ei;
    const int* dst = ei + N_EDGES;

    cudaFuncSetAttribute(gemm_kernel,
                         cudaFuncAttributeMaxDynamicSharedMemorySize, GEMM_SMEM);

    float *h0p, *Ap, *Bp;
    int *degp;
    cudaGetSymbolAddress((void**)&h0p, g_h0);
    cudaGetSymbolAddress((void**)&Ap, g_bufA);
    cudaGetSymbolAddress((void**)&Bp, g_bufB);
    cudaGetSymbolAddress((void**)&degp, g_deg);

    // order: memset(1), deg(2), scan(3), fill(4), gemm(5 - profiled), mlp(6), hops...
    cudaMemsetAsync(degp, 0, 2 * N_NODES * sizeof(int), 0);

    deg_kernel<<<(N_EDGES + 255) / 256, 256>>>(src, dst);
    scan_fused_kernel<<<1, SCAN_T>>>();
    fill_csr_kernel<<<(N_EDGES + 255) / 256, 256>>>(src, dst);

    gemm_kernel<<<(N_NODES + GB_ROWS - 1) / GB_ROWS, GB_ROWS, GEMM_SMEM>>>(
        x, Wb, bb, scores);
    mlp_kernel<<<(N_NODES + MLP_BS - 1) / MLP_BS, MLP_BS>>>(
        scores, h0p, W1, b1, W2, b2);

    const int hop_grid = (N_NODES + NODES_PER_BLOCK - 1) / NODES_PER_BLOCK;
    const float* hin = h0p;
    for (int k = 0; k < K_HOPS; k++) {
        float* o = (k == K_HOPS - 1) ? adjust : ((k % 2 == 0) ? Ap : Bp);
        hop_kernel<<<hop_grid, HOP_BS>>>(hin, h0p, o);
        hin = o;
    }
}

// round 4
// speedup vs baseline: 1.8974x; 1.4104x over previous
#include <cuda_runtime.h>
#include <cuda_fp16.h>
#include <cstdint>

// ---------------- problem constants ----------------
#define N_NODES 100000
#define N_EDGES 1600000
#define C_IN    500
#define C       40        // n_classes
#define H       64        // hidden
#define ALPHA   0.1f
#define K_HOPS  10

// ---------------- static scratch (no allocations allowed) ----------------
__device__ __half g_h0h[N_NODES * C];       // h0 in fp16
__device__ __half g_bufA[N_NODES * C];      // hop ping
__device__ __half g_bufB[N_NODES * C];      // hop pong
__device__ int    g_deg[2 * N_NODES];       // [0..N) deg_out, [N..2N) deg_in
__device__ float  g_inv_out[N_NODES];
__device__ float  g_inv_in[N_NODES];
__device__ int    g_off[N_NODES + 1];
__device__ int    g_cursor[N_NODES];
__device__ int2   g_csr[N_EDGES];           // (src, bits(norm))

// ============================================================
// 1) scores = x @ Wb + bb   [N, 40]
//    1 row/thread, x read inline via LDG.128 (streams DRAM while
//    computing), W K-tiles (100x40 = 16KB) in static smem.
// ============================================================
#define GB_ROWS 128
#define WKT     100                         // K-tile rows of W

__global__ __launch_bounds__(GB_ROWS) void gemm_kernel(
    const float* __restrict__ x, const float* __restrict__ Wb,
    const float* __restrict__ bb, float* __restrict__ scores)
{
    __shared__ float Wt[WKT * C];           // 16000 floats? no: 100*40=4000 floats = 16KB
    __shared__ float bs[C];

    const int tid = threadIdx.x;
    if (tid < C) bs[tid] = bb[tid];

    const int row = blockIdx.x * GB_ROWS + tid;
    const float4* xrow4 = (const float4*)(x + (size_t)row * C_IN);

    float acc[C];
#pragma unroll
    for (int c = 0; c < C; c++) acc[c] = 0.f;

#pragma unroll 1
    for (int t = 0; t < C_IN / WKT; t++) {  // 5 tiles
        __syncthreads();
        const float4* wsrc = (const float4*)(Wb + t * WKT * C);
        for (int i = tid; i < WKT * C / 4; i += GB_ROWS)
            ((float4*)Wt)[i] = wsrc[i];
        __syncthreads();

        if (row < N_NODES) {
#pragma unroll 5
            for (int kg = 0; kg < WKT / 4; kg++) {    // 25 float4 groups
                const float4 xv = __ldg(xrow4 + t * (WKT / 4) + kg);
#pragma unroll
                for (int j = 0; j < 4; j++) {
                    const float xk = j == 0 ? xv.x : j == 1 ? xv.y : j == 2 ? xv.z : xv.w;
                    const float4* wr = (const float4*)(Wt + (kg * 4 + j) * C);
#pragma unroll
                    for (int c4 = 0; c4 < C / 4; c4++) {
                        const float4 w = wr[c4];
                        acc[c4 * 4 + 0] += xk * w.x;
                        acc[c4 * 4 + 1] += xk * w.y;
                        acc[c4 * 4 + 2] += xk * w.z;
                        acc[c4 * 4 + 3] += xk * w.w;
                    }
                }
            }
        }
    }

    if (row >= N_NODES) return;
    float4* out4 = (float4*)(scores + (size_t)row * C);
#pragma unroll
    for (int c4 = 0; c4 < C / 4; c4++)
        out4[c4] = make_float4(acc[c4*4+0] + bs[c4*4+0], acc[c4*4+1] + bs[c4*4+1],
                               acc[c4*4+2] + bs[c4*4+2], acc[c4*4+3] + bs[c4*4+3]);
}

// ============================================================
// 2) h0 = relu(softmax(scores) @ W1 + b1) @ W2 + b2  -> fp16
// ============================================================
#define MLP_BS 128
__global__ __launch_bounds__(MLP_BS) void mlp_kernel(
    const float* __restrict__ scores,
    const float* __restrict__ W1, const float* __restrict__ b1,
    const float* __restrict__ W2, const float* __restrict__ b2)
{
    __shared__ float W1s[C * H];
    __shared__ float W2s[H * C];
    __shared__ float b1s[H];
    __shared__ float b2s[C];
    __shared__ float p_sh[C * MLP_BS];

    const int tid = threadIdx.x;
    for (int i = tid; i < C * H; i += MLP_BS) W1s[i] = W1[i];
    for (int i = tid; i < H * C; i += MLP_BS) W2s[i] = W2[i];
    if (tid < H) b1s[tid] = b1[tid];
    if (tid < C) b2s[tid] = b2[tid];
    __syncthreads();

    const int node = blockIdx.x * MLP_BS + tid;
    if (node >= N_NODES) return;

    const float4* sc4 = (const float4*)(scores + (size_t)node * C);
    float m = -1e30f;
#pragma unroll
    for (int q = 0; q < C / 4; q++) {
        const float4 v = sc4[q];
        p_sh[(q * 4 + 0) * MLP_BS + tid] = v.x;
        p_sh[(q * 4 + 1) * MLP_BS + tid] = v.y;
        p_sh[(q * 4 + 2) * MLP_BS + tid] = v.z;
        p_sh[(q * 4 + 3) * MLP_BS + tid] = v.w;
        m = fmaxf(m, fmaxf(fmaxf(v.x, v.y), fmaxf(v.z, v.w)));
    }
    float s = 0.f;
    for (int i = 0; i < C; i++) {
        const float e = __expf(p_sh[i * MLP_BS + tid] - m);
        p_sh[i * MLP_BS + tid] = e;
        s += e;
    }
    const float inv = 1.f / s;

    float h1[H];
#pragma unroll
    for (int j = 0; j < H; j++) h1[j] = b1s[j];
    for (int i = 0; i < C; i++) {
        const float pv = p_sh[i * MLP_BS + tid] * inv;
#pragma unroll
        for (int j = 0; j < H; j++) h1[j] += pv * W1s[i * H + j];
    }
#pragma unroll
    for (int j = 0; j < H; j++) h1[j] = fmaxf(h1[j], 0.f);

    float o[C];
    for (int c = 0; c < C; c++) {
        float a = b2s[c];
#pragma unroll
        for (int j = 0; j < H; j++) a += h1[j] * W2s[j * C + c];
        o[c] = a;
    }

    // pack to fp16 and store as 5 x uint4 (80B row)
    uint4 pk[5];
    uint32_t* pw = (uint32_t*)pk;
#pragma unroll
    for (int p = 0; p < C / 2; p++) {
        const __half2 hv = __floats2half2_rn(o[2 * p], o[2 * p + 1]);
        pw[p] = *(const uint32_t*)&hv;
    }
    uint4* hrow = (uint4*)(g_h0h + (size_t)node * C);
#pragma unroll
    for (int p = 0; p < 5; p++) hrow[p] = pk[p];
}

// ============================================================
// 3) degrees
// ============================================================
__global__ void deg_kernel(const int* __restrict__ src, const int* __restrict__ dst)
{
    const int e = blockIdx.x * blockDim.x + threadIdx.x;
    if (e < N_EDGES) {
        atomicAdd(&g_deg[src[e]], 1);
        atomicAdd(&g_deg[N_NODES + dst[e]], 1);
    }
}

// ============================================================
// 4) fused: inv-sqrt + exclusive scan -> offsets + cursor
// ============================================================
#define SCAN_T 1024
__global__ __launch_bounds__(SCAN_T) void scan_fused_kernel()
{
    __shared__ int part[SCAN_T];
    const int t = threadIdx.x;

    for (int i = t; i < N_NODES; i += SCAN_T) {
        const int d_o = g_deg[i];
        const int d_i = g_deg[N_NODES + i];
        g_inv_out[i] = d_o > 0 ? rsqrtf((float)d_o) : 0.f;
        g_inv_in[i]  = d_i > 0 ? rsqrtf((float)d_i) : 0.f;
    }

    const int CH = (N_NODES + SCAN_T - 1) / SCAN_T;
    const int base = t * CH;
    int s = 0;
    for (int i = 0; i < CH; i++) {
        const int idx = base + i;
        if (idx < N_NODES) s += g_deg[N_NODES + idx];
    }
    part[t] = s;
    __syncthreads();
    for (int o = 1; o < SCAN_T; o <<= 1) {
        const int v = (t >= o) ? part[t - o] : 0;
        __syncthreads();
        part[t] += v;
        __syncthreads();
    }
    int excl = part[t] - s;
    for (int i = 0; i < CH; i++) {
        const int idx = base + i;
        if (idx < N_NODES) {
            g_off[idx] = excl;
            g_cursor[idx] = excl;
            excl += g_deg[N_NODES + idx];
        }
    }
    if (t == SCAN_T - 1) g_off[N_NODES] = part[SCAN_T - 1];
}

// ============================================================
// 5) CSR fill (single 8B scatter per edge)
// ============================================================
__global__ void fill_csr_kernel(const int* __restrict__ src, const int* __restrict__ dst)
{
    const int e = blockIdx.x * blockDim.x + threadIdx.x;
    if (e < N_EDGES) {
        const int s = src[e];
        const int d = dst[e];
        const int pos = atomicAdd(&g_cursor[d], 1);
        g_csr[pos] = make_int2(s, __float_as_int(g_inv_out[s] * g_inv_in[d]));
    }
}

// ============================================================
// 6) one APPNP hop, fp16 storage / fp32 accumulate.
//    5 lanes/node (uint4 = 8 halfs each), 6 nodes/warp.
// ============================================================
#define HOP_BS 256
#define NPW 6                                // nodes per warp
#define NPB ((HOP_BS / 32) * NPW)            // nodes per block = 48

template <bool LAST>
__global__ __launch_bounds__(HOP_BS) void hop_kernel(
    const __half* __restrict__ hin, const __half* __restrict__ h0,
    __half* __restrict__ hout_h, float* __restrict__ hout_f)
{
    const int warp = threadIdx.x >> 5;
    const int lane = threadIdx.x & 31;
    const int sub = lane / 5;                // 0..5 active, lanes 30,31 idle
    const int q = lane - sub * 5;            // uint4 index within 80B row
    if (sub >= NPW) return;

    const int node = (blockIdx.x * (HOP_BS / 32) + warp) * NPW + sub;
    if (node >= N_NODES) return;

    const int beg = g_off[node];
    const int end = g_off[node + 1];

    float acc[8];
#pragma unroll
    for (int i = 0; i < 8; i++) acc[i] = 0.f;

#pragma unroll 4
    for (int e = beg; e < end; e++) {
        const int2 en = __ldg(&g_csr[e]);
        const float nrm = __int_as_float(en.y);
        const uint4 hv = __ldg((const uint4*)(hin + (size_t)en.x * C) + q);
        const __half2* hp = (const __half2*)&hv;
#pragma unroll
        for (int i = 0; i < 4; i++) {
            const float2 f = __half22float2(hp[i]);
            acc[2 * i + 0] += nrm * f.x;
            acc[2 * i + 1] += nrm * f.y;
        }
    }

    const uint4 h0v = __ldg((const uint4*)(h0 + (size_t)node * C) + q);
    const __half2* h0p = (const __half2*)&h0v;
    float o[8];
#pragma unroll
    for (int i = 0; i < 4; i++) {
        const float2 f = __half22float2(h0p[i]);
        o[2 * i + 0] = (1.f - ALPHA) * acc[2 * i + 0] + ALPHA * f.x;
        o[2 * i + 1] = (1.f - ALPHA) * acc[2 * i + 1] + ALPHA * f.y;
    }

    if (LAST) {
        float4* dst = (float4*)(hout_f + (size_t)node * C + q * 8);
        dst[0] = make_float4(o[0], o[1], o[2], o[3]);
        dst[1] = make_float4(o[4], o[5], o[6], o[7]);
    } else {
        uint4 pk;
        uint32_t* pw = (uint32_t*)&pk;
#pragma unroll
        for (int i = 0; i < 4; i++) {
            const __half2 hv = __floats2half2_rn(o[2 * i], o[2 * i + 1]);
            pw[i] = *(const uint32_t*)&hv;
        }
        ((uint4*)(hout_h + (size_t)node * C))[q] = pk;
    }
}

// ============================================================
// launch
// ============================================================
extern "C" void kernel_launch(void* const* d_in, const int* in_sizes, int n_in,
                              void* d_out, int out_size)
{
    const float* x  = (const float*)d_in[0];
    const int*   ei = (const int*)d_in[1];
    const float* Wb = (const float*)d_in[2];
    const float* bb = (const float*)d_in[3];
    const float* W1 = (const float*)d_in[4];
    const float* b1 = (const float*)d_in[5];
    const float* W2 = (const float*)d_in[6];
    const float* b2 = (const float*)d_in[7];

    float* out = (float*)d_out;
    float* adjust = out;                              // [N, 40]
    float* scores = out + (size_t)N_NODES * C;        // [N, 40]

    const int* src = ei;
    const int* dst = ei + N_EDGES;

    __half *h0p, *Ap, *Bp;
    int *degp;
    cudaGetSymbolAddress((void**)&h0p, g_h0h);
    cudaGetSymbolAddress((void**)&Ap, g_bufA);
    cudaGetSymbolAddress((void**)&Bp, g_bufB);
    cudaGetSymbolAddress((void**)&degp, g_deg);

    // order: memset(1), deg(2), scan(3), fill(4), gemm(5 - profiled), mlp(6), hops...
    cudaMemsetAsync(degp, 0, 2 * N_NODES * sizeof(int), 0);

    deg_kernel<<<(N_EDGES + 255) / 256, 256>>>(src, dst);
    scan_fused_kernel<<<1, SCAN_T>>>();
    fill_csr_kernel<<<(N_EDGES + 255) / 256, 256>>>(src, dst);

    gemm_kernel<<<(N_NODES + GB_ROWS - 1) / GB_ROWS, GB_ROWS>>>(x, Wb, bb, scores);
    mlp_kernel<<<(N_NODES + MLP_BS - 1) / MLP_BS, MLP_BS>>>(scores, W1, b1, W2, b2);

    const int hop_grid = (N_NODES + NPB - 1) / NPB;
    const __half* hin = h0p;
    for (int k = 0; k < K_HOPS; k++) {
        if (k == K_HOPS - 1) {
            hop_kernel<true><<<hop_grid, HOP_BS>>>(hin, h0p, nullptr, adjust);
        } else {
            __half* o = (k % 2 == 0) ? Ap : Bp;
            hop_kernel<false><<<hop_grid, HOP_BS>>>(hin, h0p, o, nullptr);
            hin = o;
        }
    }
}

// round 6
// speedup vs baseline: 1.9789x; 1.0429x over previous
#include <cuda_runtime.h>
#include <cuda_fp16.h>
#include <cstdint>

// ---------------- problem constants ----------------
#define N_NODES 100000
#define N_EDGES 1600000
#define C_IN    500
#define C       40        // n_classes
#define H       64        // hidden
#define ALPHA   0.1f
#define K_HOPS  10

// ---------------- static scratch (no allocations allowed) ----------------
__device__ __half g_h0h[N_NODES * C];       // h0 in fp16
__device__ __half g_bufA[N_NODES * C];      // hop ping
__device__ __half g_bufB[N_NODES * C];      // hop pong
__device__ int    g_deg[2 * N_NODES];       // [0..N) deg_out, [N..2N) deg_in
__device__ float  g_inv_out[N_NODES];
__device__ float  g_inv_in[N_NODES];
__device__ int    g_off[N_NODES + 1];
__device__ int    g_cursor[N_NODES];
__device__ int2   g_csr[N_EDGES];           // (src, bits(norm))

// ============================================================
// 1) scores = x @ Wb + bb   [N, 40]
//    2 rows/thread, packed fma.rn.f32x2 accumulators.
//    W K-tiles (100x40 = 16KB, 16B-aligned) in smem; x streamed
//    inline via LDG.128.
// ============================================================
#define GB_T 128
#define WKT  100

__global__ __launch_bounds__(GB_T, 2) void gemm_kernel(
    const float* __restrict__ x, const float* __restrict__ Wb,
    const float* __restrict__ bb, float* __restrict__ scores)
{
    __shared__ __align__(16) float Wt[WKT * C];
    __shared__ float bs[C];

    const int tid = threadIdx.x;
    if (tid < C) bs[tid] = bb[tid];

    const int r0 = blockIdx.x * 256 + tid;          // always < N (grid=391)
    const int r1 = r0 + 128;
    const size_t r1c = (r1 < N_NODES) ? (size_t)r1 : (size_t)(N_NODES - 1);
    const float4* xa_p = (const float4*)(x + (size_t)r0 * C_IN);
    const float4* xb_p = (const float4*)(x + r1c * C_IN);

    unsigned long long acc0[C / 2], acc1[C / 2];
#pragma unroll
    for (int j = 0; j < C / 2; j++) { acc0[j] = 0ull; acc1[j] = 0ull; }

#pragma unroll 1
    for (int t = 0; t < C_IN / WKT; t++) {          // 5 tiles of K=100
        __syncthreads();
        const float4* wsrc = (const float4*)(Wb + t * WKT * C);
        for (int i = tid; i < WKT * C / 4; i += GB_T)
            ((float4*)Wt)[i] = wsrc[i];
        __syncthreads();

#pragma unroll 1
        for (int kg = 0; kg < WKT / 4; kg++) {      // 25 groups of 4 k's
            const float4 xa = __ldg(xa_p + t * (WKT / 4) + kg);
            const float4 xb = __ldg(xb_p + t * (WKT / 4) + kg);
#pragma unroll
            for (int j = 0; j < 4; j++) {
                const float fa = j == 0 ? xa.x : j == 1 ? xa.y : j == 2 ? xa.z : xa.w;
                const float fb = j == 0 ? xb.x : j == 1 ? xb.y : j == 2 ? xb.z : xb.w;
                unsigned long long xa2, xb2;
                asm("mov.b64 %0, {%1, %1};" : "=l"(xa2) : "f"(fa));
                asm("mov.b64 %0, {%1, %1};" : "=l"(xb2) : "f"(fb));
                const ulonglong2* wr = (const ulonglong2*)(Wt + (kg * 4 + j) * C);
#pragma unroll
                for (int p = 0; p < C / 4; p++) {   // 10 LDS.128 = 20 pairs
                    const ulonglong2 w = wr[p];
                    asm("fma.rn.f32x2 %0, %1, %2, %0;" : "+l"(acc0[2*p  ]) : "l"(w.x), "l"(xa2));
                    asm("fma.rn.f32x2 %0, %1, %2, %0;" : "+l"(acc0[2*p+1]) : "l"(w.y), "l"(xa2));
                    asm("fma.rn.f32x2 %0, %1, %2, %0;" : "+l"(acc1[2*p  ]) : "l"(w.x), "l"(xb2));
                    asm("fma.rn.f32x2 %0, %1, %2, %0;" : "+l"(acc1[2*p+1]) : "l"(w.y), "l"(xb2));
                }
            }
        }
    }

    float o0[C], o1[C];
#pragma unroll
    for (int j = 0; j < C / 2; j++) {
        float lo, hi;
        asm("mov.b64 {%0, %1}, %2;" : "=f"(lo), "=f"(hi) : "l"(acc0[j]));
        o0[2*j] = lo + bs[2*j]; o0[2*j+1] = hi + bs[2*j+1];
        asm("mov.b64 {%0, %1}, %2;" : "=f"(lo), "=f"(hi) : "l"(acc1[j]));
        o1[2*j] = lo + bs[2*j]; o1[2*j+1] = hi + bs[2*j+1];
    }
    float4* d0 = (float4*)(scores + (size_t)r0 * C);
#pragma unroll
    for (int c4 = 0; c4 < C / 4; c4++)
        d0[c4] = make_float4(o0[c4*4], o0[c4*4+1], o0[c4*4+2], o0[c4*4+3]);
    if (r1 < N_NODES) {
        float4* d1 = (float4*)(scores + (size_t)r1 * C);
#pragma unroll
        for (int c4 = 0; c4 < C / 4; c4++)
            d1[c4] = make_float4(o1[c4*4], o1[c4*4+1], o1[c4*4+2], o1[c4*4+3]);
    }
}

// ============================================================
// 2) h0 = relu(softmax(scores) @ W1 + b1) @ W2 + b2  -> fp16
// ============================================================
#define MLP_BS 128
__global__ __launch_bounds__(MLP_BS) void mlp_kernel(
    const float* __restrict__ scores,
    const float* __restrict__ W1, const float* __restrict__ b1,
    const float* __restrict__ W2, const float* __restrict__ b2)
{
    __shared__ float W1s[C * H];
    __shared__ float W2s[H * C];
    __shared__ float b1s[H];
    __shared__ float b2s[C];
    __shared__ float p_sh[C * MLP_BS];

    const int tid = threadIdx.x;
    for (int i = tid; i < C * H; i += MLP_BS) W1s[i] = W1[i];
    for (int i = tid; i < H * C; i += MLP_BS) W2s[i] = W2[i];
    if (tid < H) b1s[tid] = b1[tid];
    if (tid < C) b2s[tid] = b2[tid];
    __syncthreads();

    const int node = blockIdx.x * MLP_BS + tid;
    if (node >= N_NODES) return;

    const float4* sc4 = (const float4*)(scores + (size_t)node * C);
    float m = -1e30f;
#pragma unroll
    for (int q = 0; q < C / 4; q++) {
        const float4 v = sc4[q];
        p_sh[(q * 4 + 0) * MLP_BS + tid] = v.x;
        p_sh[(q * 4 + 1) * MLP_BS + tid] = v.y;
        p_sh[(q * 4 + 2) * MLP_BS + tid] = v.z;
        p_sh[(q * 4 + 3) * MLP_BS + tid] = v.w;
        m = fmaxf(m, fmaxf(fmaxf(v.x, v.y), fmaxf(v.z, v.w)));
    }
    float s = 0.f;
    for (int i = 0; i < C; i++) {
        const float e = __expf(p_sh[i * MLP_BS + tid] - m);
        p_sh[i * MLP_BS + tid] = e;
        s += e;
    }
    const float inv = 1.f / s;

    float h1[H];
#pragma unroll
    for (int j = 0; j < H; j++) h1[j] = b1s[j];
    for (int i = 0; i < C; i++) {
        const float pv = p_sh[i * MLP_BS + tid] * inv;
#pragma unroll
        for (int j = 0; j < H; j++) h1[j] += pv * W1s[i * H + j];
    }
#pragma unroll
    for (int j = 0; j < H; j++) h1[j] = fmaxf(h1[j], 0.f);

    float o[C];
    for (int c = 0; c < C; c++) {
        float a = b2s[c];
#pragma unroll
        for (int j = 0; j < H; j++) a += h1[j] * W2s[j * C + c];
        o[c] = a;
    }

    // pack to fp16 and store as 5 x uint4 (80B row)
    uint4 pk[5];
    uint32_t* pw = (uint32_t*)pk;
#pragma unroll
    for (int p = 0; p < C / 2; p++) {
        const __half2 hv = __floats2half2_rn(o[2 * p], o[2 * p + 1]);
        pw[p] = *(const uint32_t*)&hv;
    }
    uint4* hrow = (uint4*)(g_h0h + (size_t)node * C);
#pragma unroll
    for (int p = 0; p < 5; p++) hrow[p] = pk[p];
}

// ============================================================
// 3) degrees
// ============================================================
__global__ void deg_kernel(const int* __restrict__ src, const int* __restrict__ dst)
{
    const int e = blockIdx.x * blockDim.x + threadIdx.x;
    if (e < N_EDGES) {
        atomicAdd(&g_deg[src[e]], 1);
        atomicAdd(&g_deg[N_NODES + dst[e]], 1);
    }
}

// ============================================================
// 4) fused: inv-sqrt + exclusive scan -> offsets + cursor
// ============================================================
#define SCAN_T 1024
__global__ __launch_bounds__(SCAN_T) void scan_fused_kernel()
{
    __shared__ int part[SCAN_T];
    const int t = threadIdx.x;

    for (int i = t; i < N_NODES; i += SCAN_T) {
        const int d_o = g_deg[i];
        const int d_i = g_deg[N_NODES + i];
        g_inv_out[i] = d_o > 0 ? rsqrtf((float)d_o) : 0.f;
        g_inv_in[i]  = d_i > 0 ? rsqrtf((float)d_i) : 0.f;
    }

    const int CH = (N_NODES + SCAN_T - 1) / SCAN_T;
    const int base = t * CH;
    int s = 0;
    for (int i = 0; i < CH; i++) {
        const int idx = base + i;
        if (idx < N_NODES) s += g_deg[N_NODES + idx];
    }
    part[t] = s;
    __syncthreads();
    for (int o = 1; o < SCAN_T; o <<= 1) {
        const int v = (t >= o) ? part[t - o] : 0;
        __syncthreads();
        part[t] += v;
        __syncthreads();
    }
    int excl = part[t] - s;
    for (int i = 0; i < CH; i++) {
        const int idx = base + i;
        if (idx < N_NODES) {
            g_off[idx] = excl;
            g_cursor[idx] = excl;
            excl += g_deg[N_NODES + idx];
        }
    }
    if (t == SCAN_T - 1) g_off[N_NODES] = part[SCAN_T - 1];
}

// ============================================================
// 5) CSR fill (single 8B scatter per edge)
// ============================================================
__global__ void fill_csr_kernel(const int* __restrict__ src, const int* __restrict__ dst)
{
    const int e = blockIdx.x * blockDim.x + threadIdx.x;
    if (e < N_EDGES) {
        const int s = src[e];
        const int d = dst[e];
        const int pos = atomicAdd(&g_cursor[d], 1);
        g_csr[pos] = make_int2(s, __float_as_int(g_inv_out[s] * g_inv_in[d]));
    }
}

// ============================================================
// 6) one APPNP hop, fp16 storage / fp32 accumulate.
//    5 lanes/node (uint4 = 8 halfs each), 6 nodes/warp.
// ============================================================
#define HOP_BS 256
#define NPW 6                                // nodes per warp
#define NPB ((HOP_BS / 32) * NPW)            // nodes per block = 48

template <bool LAST>
__global__ __launch_bounds__(HOP_BS) void hop_kernel(
    const __half* __restrict__ hin, const __half* __restrict__ h0,
    __half* __restrict__ hout_h, float* __restrict__ hout_f)
{
    const int warp = threadIdx.x >> 5;
    const int lane = threadIdx.x & 31;
    const int sub = lane / 5;                // 0..5 active, lanes 30,31 idle
    const int q = lane - sub * 5;            // uint4 index within 80B row
    if (sub >= NPW) return;

    const int node = (blockIdx.x * (HOP_BS / 32) + warp) * NPW + sub;
    if (node >= N_NODES) return;

    const int beg = g_off[node];
    const int end = g_off[node + 1];

    float acc[8];
#pragma unroll
    for (int i = 0; i < 8; i++) acc[i] = 0.f;

#pragma unroll 4
    for (int e = beg; e < end; e++) {
        const int2 en = __ldg(&g_csr[e]);
        const float nrm = __int_as_float(en.y);
        const uint4 hv = __ldg((const uint4*)(hin + (size_t)en.x * C) + q);
        const __half2* hp = (const __half2*)&hv;
#pragma unroll
        for (int i = 0; i < 4; i++) {
            const float2 f = __half22float2(hp[i]);
            acc[2 * i + 0] += nrm * f.x;
            acc[2 * i + 1] += nrm * f.y;
        }
    }

    const uint4 h0v = __ldg((const uint4*)(h0 + (size_t)node * C) + q);
    const __half2* h0p = (const __half2*)&h0v;
    float o[8];
#pragma unroll
    for (int i = 0; i < 4; i++) {
        const float2 f = __half22float2(h0p[i]);
        o[2 * i + 0] = (1.f - ALPHA) * acc[2 * i + 0] + ALPHA * f.x;
        o[2 * i + 1] = (1.f - ALPHA) * acc[2 * i + 1] + ALPHA * f.y;
    }

    if (LAST) {
        float4* dst = (float4*)(hout_f + (size_t)node * C + q * 8);
        dst[0] = make_float4(o[0], o[1], o[2], o[3]);
        dst[1] = make_float4(o[4], o[5], o[6], o[7]);
    } else {
        uint4 pk;
        uint32_t* pw = (uint32_t*)&pk;
#pragma unroll
        for (int i = 0; i < 4; i++) {
            const __half2 hv = __floats2half2_rn(o[2 * i], o[2 * i + 1]);
            pw[i] = *(const uint32_t*)&hv;
        }
        ((uint4*)(hout_h + (size_t)node * C))[q] = pk;
    }
}

// ============================================================
// launch
// ============================================================
extern "C" void kernel_launch(void* const* d_in, const int* in_sizes, int n_in,
                              void* d_out, int out_size)
{
    const float* x  = (const float*)d_in[0];
    const int*   ei = (const int*)d_in[1];
    const float* Wb = (const float*)d_in[2];
    const float* bb = (const float*)d_in[3];
    const float* W1 = (const float*)d_in[4];
    const float* b1 = (const float*)d_in[5];
    const float* W2 = (const float*)d_in[6];
    const float* b2 = (const float*)d_in[7];

    float* out = (float*)d_out;
    float* adjust = out;                              // [N, 40]
    float* scores = out + (size_t)N_NODES * C;        // [N, 40]

    const int* src = ei;
    const int* dst = ei + N_EDGES;

    __half *h0p, *Ap, *Bp;
    int *degp;
    cudaGetSymbolAddress((void**)&h0p, g_h0h);
    cudaGetSymbolAddress((void**)&Ap, g_bufA);
    cudaGetSymbolAddress((void**)&Bp, g_bufB);
    cudaGetSymbolAddress((void**)&degp, g_deg);

    // order: memset(1), deg(2), scan(3), fill(4), gemm(5 - profiled), mlp(6), hops...
    cudaMemsetAsync(degp, 0, 2 * N_NODES * sizeof(int), 0);

    deg_kernel<<<(N_EDGES + 255) / 256, 256>>>(src, dst);
    scan_fused_kernel<<<1, SCAN_T>>>();
    fill_csr_kernel<<<(N_EDGES + 255) / 256, 256>>>(src, dst);

    gemm_kernel<<<(N_NODES + 255) / 256, GB_T>>>(x, Wb, bb, scores);
    mlp_kernel<<<(N_NODES + MLP_BS - 1) / MLP_BS, MLP_BS>>>(scores, W1, b1, W2, b2);

    const int hop_grid = (N_NODES + NPB - 1) / NPB;
    const __half* hin = h0p;
    for (int k = 0; k < K_HOPS; k++) {
        if (k == K_HOPS - 1) {
            hop_kernel<true><<<hop_grid, HOP_BS>>>(hin, h0p, nullptr, adjust);
        } else {
            __half* o = (k % 2 == 0) ? Ap : Bp;
            hop_kernel<false><<<hop_grid, HOP_BS>>>(hin, h0p, o, nullptr);
            hin = o;
        }
    }
}